// round 14
// baseline (speedup 1.0000x reference)
#include <cuda_runtime.h>
#include <cstdint>
#include <cstddef>

typedef unsigned long long u64;
typedef unsigned int u32;

#define B_SZ 64
#define T_SZ 2048
#define H_SZ 256
#define G4   1024   // 4*H

// scratch: natural layout [m][gate*256+u] (gemm output)
__device__ float g_xg[(size_t)B_SZ * T_SZ * G4];
// scratch: gate-interleaved layout [m][u*4+gate] (scan input)
__device__ float g_xgi[(size_t)B_SZ * T_SZ * G4];

// ---------------- f32x2 helpers ----------------
__device__ __forceinline__ u64 pk2(float lo, float hi) {
    u64 r; asm("mov.b64 %0, {%1, %2};" : "=l"(r) : "f"(lo), "f"(hi)); return r;
}
__device__ __forceinline__ u64 dup2(float a) {
    u64 r; asm("mov.b64 %0, {%1, %1};" : "=l"(r) : "f"(a)); return r;
}
__device__ __forceinline__ u64 fma2(u64 a, u64 b, u64 c) {
    u64 d; asm("fma.rn.f32x2 %0, %1, %2, %3;" : "=l"(d) : "l"(a), "l"(b), "l"(c)); return d;
}
__device__ __forceinline__ u64 add2(u64 a, u64 b) {
    u64 d; asm("add.rn.f32x2 %0, %1, %2;" : "=l"(d) : "l"(a), "l"(b)); return d;
}
__device__ __forceinline__ void unpk(u64 v, float& lo, float& hi) {
    asm("mov.b64 {%0, %1}, %2;" : "=f"(lo), "=f"(hi) : "l"(v));
}

// ---------------- cluster / mbarrier helpers ----------------
__device__ __forceinline__ u32 smem_u32(const void* p) {
    u32 a;
    asm("{ .reg .u64 t; cvta.to.shared.u64 t, %1; cvt.u32.u64 %0, t; }" : "=r"(a) : "l"(p));
    return a;
}
__device__ __forceinline__ u32 mapa_sh(u32 a, u32 rk) {
    u32 r; asm("mapa.shared::cluster.u32 %0, %1, %2;" : "=r"(r) : "r"(a), "r"(rk)); return r;
}
__device__ __forceinline__ void cluster_sync_() {
    asm volatile("barrier.cluster.arrive.aligned;" ::: "memory");
    asm volatile("barrier.cluster.wait.aligned;" ::: "memory");
}
__device__ __forceinline__ void mbar_init(u32 a, u32 cnt) {
    asm volatile("mbarrier.init.shared.b64 [%0], %1;" :: "r"(a), "r"(cnt) : "memory");
}
__device__ __forceinline__ void mbar_expect(u32 a, u32 bytes) {
    asm volatile("mbarrier.arrive.expect_tx.shared.b64 _, [%0], %1;" :: "r"(a), "r"(bytes) : "memory");
}
__device__ __forceinline__ void mbar_wait(u32 a, u32 ph) {
    asm volatile(
        "{\n\t.reg .pred P;\n\t"
        "MW%=:\n\t"
        "mbarrier.try_wait.parity.acquire.cta.shared::cta.b64 P, [%0], %1, 0x989680;\n\t"
        "@!P bra MW%=;\n\t}"
        :: "r"(a), "r"(ph) : "memory");
}
__device__ __forceinline__ void st_async_f32(u32 dst, float v, u32 mb) {
    asm volatile(
        "st.async.shared::cluster.mbarrier::complete_tx::bytes.b32 [%0], %1, [%2];"
        :: "r"(dst), "r"(__float_as_uint(v)), "r"(mb) : "memory");
}

// ---------------- activations (exact, MUFU-based) ----------------
__device__ __forceinline__ float sigm(float x) {
    return __fdividef(1.0f, 1.0f + __expf(-x));
}
__device__ __forceinline__ float tanh_(float x) {
    return 1.0f - __fdividef(2.0f, __expf(2.0f * x) + 1.0f);
}

// =====================================================================
// Phase 1: g_xg[m][1024] = x[m][256] @ W_i[256][1024] + bias
// (unchanged, proven 1.35ms)
// =====================================================================
__global__ __launch_bounds__(256, 2) void xw_gemm(
    const float* __restrict__ A,
    const float* __restrict__ W,
    const float* __restrict__ bias)
{
    __shared__ float As[2][16][132];
    __shared__ float Bs[2][16][132];

    const int tid = threadIdx.x;
    const int tx = tid & 15;
    const int ty = tid >> 4;
    const int mBase = blockIdx.y * 128;
    const int nBase = blockIdx.x * 128;

    const int arow0 = tid >> 2,         akq0 = tid & 3;
    const int arow1 = (tid + 256) >> 2, akq1 = (tid + 256) & 3;
    const int bk0   = tid >> 5,         bnq0 = tid & 31;
    const int bk1   = (tid + 256) >> 5, bnq1 = (tid + 256) & 31;

    u64 acc[8][4];
    {
        const float* bp = bias + nBase + tx * 8;
        u64 b0 = pk2(bp[0], bp[1]);
        u64 b1 = pk2(bp[2], bp[3]);
        u64 b2 = pk2(bp[4], bp[5]);
        u64 b3 = pk2(bp[6], bp[7]);
#pragma unroll
        for (int i = 0; i < 8; i++) { acc[i][0] = b0; acc[i][1] = b1; acc[i][2] = b2; acc[i][3] = b3; }
    }

    float4 a_r0, a_r1, b_r0, b_r1;
    a_r0 = *(const float4*)(A + (size_t)(mBase + arow0) * 256 + akq0 * 4);
    a_r1 = *(const float4*)(A + (size_t)(mBase + arow1) * 256 + akq1 * 4);
    b_r0 = *(const float4*)(W + (size_t)bk0 * 1024 + nBase + bnq0 * 4);
    b_r1 = *(const float4*)(W + (size_t)bk1 * 1024 + nBase + bnq1 * 4);
    As[0][akq0 * 4 + 0][arow0] = a_r0.x; As[0][akq0 * 4 + 1][arow0] = a_r0.y;
    As[0][akq0 * 4 + 2][arow0] = a_r0.z; As[0][akq0 * 4 + 3][arow0] = a_r0.w;
    As[0][akq1 * 4 + 0][arow1] = a_r1.x; As[0][akq1 * 4 + 1][arow1] = a_r1.y;
    As[0][akq1 * 4 + 2][arow1] = a_r1.z; As[0][akq1 * 4 + 3][arow1] = a_r1.w;
    *(float4*)&Bs[0][bk0][bnq0 * 4] = b_r0;
    *(float4*)&Bs[0][bk1][bnq1 * 4] = b_r1;
    __syncthreads();

    int p = 0;
#pragma unroll 1
    for (int kc = 0; kc < 16; kc++) {
        if (kc < 15) {
            const int kb = (kc + 1) * 16;
            a_r0 = *(const float4*)(A + (size_t)(mBase + arow0) * 256 + kb + akq0 * 4);
            a_r1 = *(const float4*)(A + (size_t)(mBase + arow1) * 256 + kb + akq1 * 4);
            b_r0 = *(const float4*)(W + (size_t)(kb + bk0) * 1024 + nBase + bnq0 * 4);
            b_r1 = *(const float4*)(W + (size_t)(kb + bk1) * 1024 + nBase + bnq1 * 4);
        }
#pragma unroll
        for (int k = 0; k < 16; k++) {
            float4 a0 = *(float4*)&As[p][k][ty * 8];
            float4 a1 = *(float4*)&As[p][k][ty * 8 + 4];
            float4 b0 = *(float4*)&Bs[p][k][tx * 8];
            float4 b1 = *(float4*)&Bs[p][k][tx * 8 + 4];
            u64 bb0 = pk2(b0.x, b0.y), bb1 = pk2(b0.z, b0.w);
            u64 bb2 = pk2(b1.x, b1.y), bb3 = pk2(b1.z, b1.w);
            float aa[8] = {a0.x, a0.y, a0.z, a0.w, a1.x, a1.y, a1.z, a1.w};
#pragma unroll
            for (int i = 0; i < 8; i++) {
                u64 ad = dup2(aa[i]);
                acc[i][0] = fma2(ad, bb0, acc[i][0]);
                acc[i][1] = fma2(ad, bb1, acc[i][1]);
                acc[i][2] = fma2(ad, bb2, acc[i][2]);
                acc[i][3] = fma2(ad, bb3, acc[i][3]);
            }
        }
        if (kc < 15) {
            const int pn = p ^ 1;
            As[pn][akq0 * 4 + 0][arow0] = a_r0.x; As[pn][akq0 * 4 + 1][arow0] = a_r0.y;
            As[pn][akq0 * 4 + 2][arow0] = a_r0.z; As[pn][akq0 * 4 + 3][arow0] = a_r0.w;
            As[pn][akq1 * 4 + 0][arow1] = a_r1.x; As[pn][akq1 * 4 + 1][arow1] = a_r1.y;
            As[pn][akq1 * 4 + 2][arow1] = a_r1.z; As[pn][akq1 * 4 + 3][arow1] = a_r1.w;
            *(float4*)&Bs[pn][bk0][bnq0 * 4] = b_r0;
            *(float4*)&Bs[pn][bk1][bnq1 * 4] = b_r1;
            __syncthreads();
            p = pn;
        }
    }

#pragma unroll
    for (int i = 0; i < 8; i++) {
        float o[8];
        unpk(acc[i][0], o[0], o[1]); unpk(acc[i][1], o[2], o[3]);
        unpk(acc[i][2], o[4], o[5]); unpk(acc[i][3], o[6], o[7]);
        float* cp = g_xg + (size_t)(mBase + ty * 8 + i) * 1024 + nBase + tx * 8;
        *(float4*)(cp)     = make_float4(o[0], o[1], o[2], o[3]);
        *(float4*)(cp + 4) = make_float4(o[4], o[5], o[6], o[7]);
    }
}

// =====================================================================
// Repack: [m][gate*256+u] -> [m][u*4+gate]. (unchanged)
// =====================================================================
__global__ __launch_bounds__(256, 8) void repack()
{
    const size_t m = blockIdx.x;
    const int u = threadIdx.x;
    const float* src = g_xg + m * 1024;
    float4 v;
    v.x = src[u];
    v.y = src[256 + u];
    v.z = src[512 + u];
    v.w = src[768 + u];
    *(float4*)(g_xgi + m * 1024 + (size_t)u * 4) = v;
}

// =====================================================================
// Phase 2: recurrent scan, 16 clusters x (2 groups x 2 rows).
// Grid (8,16), cluster (8,1,1). Cluster cg owns rows 4*cg..4*cg+3:
// group 0 = rows +0..1, group 1 = rows +2..3. Per step the CTA runs
// segment(g=0) then segment(g=1); each segment has HALF the FMA work
// of R13 (acc[2][4]) so the pair is shorter while interleave still
// covers the DSMEM flight. rr = ks&1; act lanes ks<2; duplicate lanes
// ks in {2,3} own the fire-and-forget out STG (h via shfl xor 2).
// hbuf[group][parity][2][128]; 4 mbarriers, expect 2048B each.
// Keeps: chain-first send, deferred re-arm, STG offload.
// =====================================================================
__global__ __launch_bounds__(256, 1) __cluster_dims__(8, 1, 1)
void lstm_scan(const float* __restrict__ Wh, float* __restrict__ out)
{
    __shared__ u64 hbuf[2][2][2][128];   // 8KB: [group][parity][row][slot]
    __shared__ u64 mbar[4];              // [group*2 + parity]

    const int tid  = threadIdx.x;
    const int w    = tid >> 5;
    const int lane = tid & 31;
    const int j4   = lane >> 3;          // unit-within-group
    const int ks   = lane & 7;           // k-slice; row = ks&1
    const int rank = blockIdx.x;
    const int cg   = blockIdx.y;         // cluster group 0..15
    const int u    = rank * 32 + w * 4 + j4;

    // --- weights packed along k: wp[g][m], k-pair kp = ks*16+m ---
    u64 wp[4][16];
#pragma unroll
    for (int m = 0; m < 16; m++) {
        const int kA = ks * 32 + 2 * m;
#pragma unroll
        for (int g = 0; g < 4; g++) {
            wp[g][m] = pk2(Wh[(size_t)kA * 1024 + g * 256 + u],
                           Wh[(size_t)(kA + 1) * 1024 + g * 256 + u]);
        }
    }

    // init: zero parity-0 buffers of both groups (2x256 u64), arm 4 mbarriers
    {
        u64* h0 = &hbuf[0][0][0][0];
        u64* h1 = &hbuf[1][0][0][0];
        h0[tid] = 0ull;
        h1[tid] = 0ull;
    }
    const u32 hb_l = smem_u32(&hbuf[0][0][0][0]);
    const u32 mb_l = smem_u32(&mbar[0]);
    if (tid == 0) {
#pragma unroll
        for (int i = 0; i < 4; i++) {
            mbar_init(mb_l + i * 8, 1);
            mbar_expect(mb_l + i * 8, 2048);
        }
    }
    __syncthreads();
    cluster_sync_();   // peers armed + parity-0 buffers zeroed everywhere

    // lane-role constants: rr = ks&1 is the row-within-group
    const int rr = ks & 1;
    const int row0 = cg * 4 + rr;         // group 0 global row
    const int row1 = cg * 4 + 2 + rr;     // group 1 global row
    const size_t xgBase0  = ((size_t)row0 * T_SZ) * 1024 + (size_t)u * 4;
    const size_t xgBase1  = ((size_t)row1 * T_SZ) * 1024 + (size_t)u * 4;
    const size_t outBase0 = ((size_t)row0 * T_SZ) * H_SZ + u;
    const size_t outBase1 = ((size_t)row1 * T_SZ) * H_SZ + u;

    // producer slot for (row rr, unit u) within a [2][128] u64 buffer
    const int kp  = u >> 1;
    const int mq  = kp & 15;
    const u32 off0 = (u32)(rr * 1024 + ((mq >> 1) * 16 + (kp >> 4) * 2 + (mq & 1)) * 8 + (u & 1) * 4);

    u32 hdst[8], mrem[8];
#pragma unroll
    for (int rk = 0; rk < 8; rk++) {
        hdst[rk] = mapa_sh(hb_l, (u32)rk) + off0;   // + group*4096 + parity*2048
        mrem[rk] = mapa_sh(mb_l, (u32)rk);          // + (group*2+parity)*8
    }

    float c0 = 0.0f, h0 = 0.0f, c1 = 0.0f, h1 = 0.0f;
    u32 ph[4] = {0, 0, 0, 0};   // phase per (group*2 + parity)

#pragma unroll 1
    for (int t = 0; t < T_SZ; t++) {
        const int b = t & 1;

#pragma unroll
        for (int g = 0; g < 2; g++) {
            const u32 moff = (u32)((g * 2 + b) * 8);

            // xg prefetch — act lanes only
            float4 xq = make_float4(0.f, 0.f, 0.f, 0.f);
            if (ks < 2)
                xq = *(const float4*)(g_xgi + (g ? xgBase1 : xgBase0) + (size_t)t * 1024);

            if (t > 0) {
                mbar_wait(mb_l + moff, ph[g * 2 + b]);
                ph[g * 2 + b] ^= 1;
            }

            // ---- partial GEMM: 2 rows x 4 gates over this 32-k slice ----
            u64 acc[2][4];
#pragma unroll
            for (int r = 0; r < 2; r++)
#pragma unroll
                for (int gg = 0; gg < 4; gg++) acc[r][gg] = 0ull;

            const u64* hbp = &hbuf[g][b][0][0];
#pragma unroll
            for (int m2 = 0; m2 < 8; m2++) {
#pragma unroll
                for (int r = 0; r < 2; r++) {
                    ulonglong2 hv = *(const ulonglong2*)(hbp + r * 128 + m2 * 16 + ks * 2);
#pragma unroll
                    for (int gg = 0; gg < 4; gg++) {
                        acc[r][gg] = fma2(hv.x, wp[gg][2 * m2],     acc[r][gg]);
                        acc[r][gg] = fma2(hv.y, wp[gg][2 * m2 + 1], acc[r][gg]);
                    }
                }
            }

            // deferred re-arm of this (group,parity) for step t+2
            if (t > 0 && tid == 0)
                mbar_expect(mb_l + moff, 2048);

            // ---- warp reduce-scatter over ks (rr = ks&1 after round 1) ----
            const bool pb = (ks & 1);
            u64 kk[4];
#pragma unroll
            for (int gg = 0; gg < 4; gg++) {
                // round 1 (xor 1): row of partner parity out, keep own row
                u64 sA = pb ? acc[0][gg] : acc[1][gg];
                u64 rA = __shfl_xor_sync(0xffffffffu, sA, 1);
                u64 k0 = add2(pb ? acc[1][gg] : acc[0][gg], rA);
                // rounds 2,3: full butterflies
                u64 k1 = add2(k0, __shfl_xor_sync(0xffffffffu, k0, 2));
                kk[gg] = add2(k1, __shfl_xor_sync(0xffffffffu, k1, 4));
            }

            float hcur = 0.0f;
            // ---- act lanes (ks<2): activations + chain-first broadcast ----
            if (ks < 2) {
                float e0, e1;
                unpk(kk[0], e0, e1); const float gi = e0 + e1 + xq.x;
                unpk(kk[1], e0, e1); const float gf = e0 + e1 + xq.y;
                unpk(kk[2], e0, e1); const float gg_ = e0 + e1 + xq.z;
                unpk(kk[3], e0, e1); const float go = e0 + e1 + xq.w;

                float cv = g ? c1 : c0;
                cv = sigm(gf) * cv + sigm(gi) * tanh_(gg_);
                hcur = sigm(go) * tanh_(cv);
                if (g) { c1 = cv; h1 = hcur; } else { c0 = cv; h0 = hcur; }

                if (t < T_SZ - 1) {
                    const u32 po = (u32)(g * 4096 + (b ^ 1) * 2048);
                    const u32 mo = (u32)((g * 2 + (b ^ 1)) * 8);
#pragma unroll
                    for (int rk = 0; rk < 8; rk++)
                        st_async_f32(hdst[rk] + po, hcur, mrem[rk] + mo);
                }
            }

            // ---- duplicate lanes (ks in {2,3}): fire-and-forget STG ----
            {
                const float hs = __shfl_xor_sync(0xffffffffu, hcur, 2);
                if (ks == 2 || ks == 3)
                    out[(g ? outBase1 : outBase0) + (size_t)t * H_SZ] = hs;
            }
        }
    }

    // finals: h_T then c_T, each [B, H], appended after Hs
    if (ks < 2) {
        float* fin = out + (size_t)B_SZ * T_SZ * H_SZ;
        fin[(size_t)row0 * H_SZ + u] = h0;
        fin[(size_t)B_SZ * H_SZ + (size_t)row0 * H_SZ + u] = c0;
        fin[(size_t)row1 * H_SZ + u] = h1;
        fin[(size_t)B_SZ * H_SZ + (size_t)row1 * H_SZ + u] = c1;
    }
}

extern "C" void kernel_launch(void* const* d_in, const int* in_sizes, int n_in,
                              void* d_out, int out_size) {
    const float* x    = (const float*)d_in[0];
    const float* W_i  = (const float*)d_in[1];
    const float* W_h  = (const float*)d_in[2];
    const float* bias = (const float*)d_in[3];
    float* out = (float*)d_out;

    dim3 g1(1024 / 128, (B_SZ * T_SZ) / 128);
    xw_gemm<<<g1, 256>>>(x, W_i, bias);

    repack<<<B_SZ * T_SZ, 256>>>();

    dim3 g2(8, 16);
    lstm_scan<<<g2, 256>>>(W_h, out);
}

// round 15
// speedup vs baseline: 1.2134x; 1.2134x over previous
#include <cuda_runtime.h>
#include <cstdint>
#include <cstddef>

typedef unsigned long long u64;
typedef unsigned int u32;

#define B_SZ 64
#define T_SZ 2048
#define H_SZ 256
#define NTILE_TOT 8192                         // 16 chunks x 512 tiles
#define PLANE ((size_t)B_SZ * T_SZ * H_SZ)     // 33,554,432 elements per gate plane

// xg as 4 gate planes: g_xgp[g*PLANE + m*256 + u] (coalesced gemm writes)
__device__ float g_xgp[4 * PLANE];
__device__ int g_tile_ctr;
__device__ int g_chunk_done[16];

// ---------------- f32x2 helpers ----------------
__device__ __forceinline__ u64 pk2(float lo, float hi) {
    u64 r; asm("mov.b64 %0, {%1, %2};" : "=l"(r) : "f"(lo), "f"(hi)); return r;
}
__device__ __forceinline__ u64 dup2(float a) {
    u64 r; asm("mov.b64 %0, {%1, %1};" : "=l"(r) : "f"(a)); return r;
}
__device__ __forceinline__ u64 fma2(u64 a, u64 b, u64 c) {
    u64 d; asm("fma.rn.f32x2 %0, %1, %2, %3;" : "=l"(d) : "l"(a), "l"(b), "l"(c)); return d;
}
__device__ __forceinline__ u64 add2(u64 a, u64 b) {
    u64 d; asm("add.rn.f32x2 %0, %1, %2;" : "=l"(d) : "l"(a), "l"(b)); return d;
}
__device__ __forceinline__ void unpk(u64 v, float& lo, float& hi) {
    asm("mov.b64 {%0, %1}, %2;" : "=f"(lo), "=f"(hi) : "l"(v));
}

// ---------------- cluster / mbarrier helpers ----------------
__device__ __forceinline__ u32 smem_u32(const void* p) {
    u32 a;
    asm("{ .reg .u64 t; cvta.to.shared.u64 t, %1; cvt.u32.u64 %0, t; }" : "=r"(a) : "l"(p));
    return a;
}
__device__ __forceinline__ u32 mapa_sh(u32 a, u32 rk) {
    u32 r; asm("mapa.shared::cluster.u32 %0, %1, %2;" : "=r"(r) : "r"(a), "r"(rk)); return r;
}
__device__ __forceinline__ void cluster_sync_() {
    asm volatile("barrier.cluster.arrive.aligned;" ::: "memory");
    asm volatile("barrier.cluster.wait.aligned;" ::: "memory");
}
__device__ __forceinline__ void mbar_init(u32 a, u32 cnt) {
    asm volatile("mbarrier.init.shared.b64 [%0], %1;" :: "r"(a), "r"(cnt) : "memory");
}
__device__ __forceinline__ void mbar_expect(u32 a, u32 bytes) {
    asm volatile("mbarrier.arrive.expect_tx.shared.b64 _, [%0], %1;" :: "r"(a), "r"(bytes) : "memory");
}
__device__ __forceinline__ void mbar_wait(u32 a, u32 ph) {
    asm volatile(
        "{\n\t.reg .pred P;\n\t"
        "MW%=:\n\t"
        "mbarrier.try_wait.parity.acquire.cta.shared::cta.b64 P, [%0], %1, 0x989680;\n\t"
        "@!P bra MW%=;\n\t}"
        :: "r"(a), "r"(ph) : "memory");
}
__device__ __forceinline__ void st_async_f32(u32 dst, float v, u32 mb) {
    asm volatile(
        "st.async.shared::cluster.mbarrier::complete_tx::bytes.b32 [%0], %1, [%2];"
        :: "r"(dst), "r"(__float_as_uint(v)), "r"(mb) : "memory");
}

// ---------------- activations (exact, MUFU-based) ----------------
__device__ __forceinline__ float sigm(float x) {
    return __fdividef(1.0f, 1.0f + __expf(-x));
}
__device__ __forceinline__ float tanh_(float x) {
    return 1.0f - __fdividef(2.0f, __expf(2.0f * x) + 1.0f);
}

// =====================================================================
// Reset the cross-kernel counters (graph-replayed every call)
// =====================================================================
__global__ void reset_ctrs() {
    if (threadIdx.x == 0) g_tile_ctr = 0;
    if (threadIdx.x < 16) g_chunk_done[threadIdx.x] = 0;
}

// =====================================================================
// Fused kernel. Grid (8,17), cluster (8,1,1).
//  blockIdx.y <  8 : scan clusters (R13-proven: 2 groups x 4 rows)
//  blockIdx.y >= 8 : 72 worker CTAs — persistent gemm in t-chunk-major
//                    order; xg written as 4 gate planes; progress via
//                    threadfence + atomicAdd(chunk_done); scan polls
//                    with an acquire load once per 128 steps.
// =====================================================================
__global__ __launch_bounds__(256, 1) __cluster_dims__(8, 1, 1)
void fused(const float* __restrict__ x, const float* __restrict__ Wi,
           const float* __restrict__ Wh, const float* __restrict__ bias,
           float* __restrict__ out)
{
    __shared__ __align__(16) char smem_raw[34048];
    const int tid = threadIdx.x;

    if (blockIdx.y >= 8) {
        // ===================== worker path (gemm) =====================
        float (*As)[16][132] = (float(*)[16][132])(smem_raw);
        float (*Bs)[16][132] = (float(*)[16][132])(smem_raw + 16896);
        int* s_task = (int*)(smem_raw + 33792);

        const int tx = tid & 15;
        const int ty = tid >> 4;
        const int arow0 = tid >> 2,         akq0 = tid & 3;
        const int arow1 = (tid + 256) >> 2, akq1 = (tid + 256) & 3;
        const int bk0   = tid >> 5,         bnq0 = tid & 31;
        const int bk1   = (tid + 256) >> 5, bnq1 = (tid + 256) & 31;

        for (;;) {
            __syncthreads();
            if (tid == 0) *s_task = atomicAdd(&g_tile_ctr, 1);
            __syncthreads();
            const int task = *s_task;
            if (task >= NTILE_TOT) break;
            const int c     = task >> 9;          // t-chunk 0..15
            const int rem   = task & 511;
            const int row   = rem >> 3;           // batch row 0..63
            const int nt    = rem & 7;            // n-tile 0..7
            const int mBase = row * 2048 + c * 128;
            const int nBase = nt * 128;

            u64 acc[8][4];
            {
                const float* bp = bias + nBase + tx * 8;
                u64 b0 = pk2(bp[0], bp[1]);
                u64 b1 = pk2(bp[2], bp[3]);
                u64 b2 = pk2(bp[4], bp[5]);
                u64 b3 = pk2(bp[6], bp[7]);
#pragma unroll
                for (int i = 0; i < 8; i++) { acc[i][0] = b0; acc[i][1] = b1; acc[i][2] = b2; acc[i][3] = b3; }
            }

            float4 a_r0, a_r1, b_r0, b_r1;
            a_r0 = *(const float4*)(x + (size_t)(mBase + arow0) * 256 + akq0 * 4);
            a_r1 = *(const float4*)(x + (size_t)(mBase + arow1) * 256 + akq1 * 4);
            b_r0 = *(const float4*)(Wi + (size_t)bk0 * 1024 + nBase + bnq0 * 4);
            b_r1 = *(const float4*)(Wi + (size_t)bk1 * 1024 + nBase + bnq1 * 4);
            As[0][akq0 * 4 + 0][arow0] = a_r0.x; As[0][akq0 * 4 + 1][arow0] = a_r0.y;
            As[0][akq0 * 4 + 2][arow0] = a_r0.z; As[0][akq0 * 4 + 3][arow0] = a_r0.w;
            As[0][akq1 * 4 + 0][arow1] = a_r1.x; As[0][akq1 * 4 + 1][arow1] = a_r1.y;
            As[0][akq1 * 4 + 2][arow1] = a_r1.z; As[0][akq1 * 4 + 3][arow1] = a_r1.w;
            *(float4*)&Bs[0][bk0][bnq0 * 4] = b_r0;
            *(float4*)&Bs[0][bk1][bnq1 * 4] = b_r1;
            __syncthreads();

            int p = 0;
#pragma unroll 1
            for (int kc = 0; kc < 16; kc++) {
                if (kc < 15) {
                    const int kb = (kc + 1) * 16;
                    a_r0 = *(const float4*)(x + (size_t)(mBase + arow0) * 256 + kb + akq0 * 4);
                    a_r1 = *(const float4*)(x + (size_t)(mBase + arow1) * 256 + kb + akq1 * 4);
                    b_r0 = *(const float4*)(Wi + (size_t)(kb + bk0) * 1024 + nBase + bnq0 * 4);
                    b_r1 = *(const float4*)(Wi + (size_t)(kb + bk1) * 1024 + nBase + bnq1 * 4);
                }
#pragma unroll
                for (int k = 0; k < 16; k++) {
                    float4 a0 = *(float4*)&As[p][k][ty * 8];
                    float4 a1 = *(float4*)&As[p][k][ty * 8 + 4];
                    float4 b0 = *(float4*)&Bs[p][k][tx * 8];
                    float4 b1 = *(float4*)&Bs[p][k][tx * 8 + 4];
                    u64 bb0 = pk2(b0.x, b0.y), bb1 = pk2(b0.z, b0.w);
                    u64 bb2 = pk2(b1.x, b1.y), bb3 = pk2(b1.z, b1.w);
                    float aa[8] = {a0.x, a0.y, a0.z, a0.w, a1.x, a1.y, a1.z, a1.w};
#pragma unroll
                    for (int i = 0; i < 8; i++) {
                        u64 ad = dup2(aa[i]);
                        acc[i][0] = fma2(ad, bb0, acc[i][0]);
                        acc[i][1] = fma2(ad, bb1, acc[i][1]);
                        acc[i][2] = fma2(ad, bb2, acc[i][2]);
                        acc[i][3] = fma2(ad, bb3, acc[i][3]);
                    }
                }
                if (kc < 15) {
                    const int pn = p ^ 1;
                    As[pn][akq0 * 4 + 0][arow0] = a_r0.x; As[pn][akq0 * 4 + 1][arow0] = a_r0.y;
                    As[pn][akq0 * 4 + 2][arow0] = a_r0.z; As[pn][akq0 * 4 + 3][arow0] = a_r0.w;
                    As[pn][akq1 * 4 + 0][arow1] = a_r1.x; As[pn][akq1 * 4 + 1][arow1] = a_r1.y;
                    As[pn][akq1 * 4 + 2][arow1] = a_r1.z; As[pn][akq1 * 4 + 3][arow1] = a_r1.w;
                    *(float4*)&Bs[pn][bk0][bnq0 * 4] = b_r0;
                    *(float4*)&Bs[pn][bk1][bnq1 * 4] = b_r1;
                    __syncthreads();
                    p = pn;
                }
            }

            // epilogue: write to gate plane (coalesced, identical pattern)
            const int gate = nt >> 1;
            const int uoff = (nt & 1) * 128;
            float* pl = g_xgp + (size_t)gate * PLANE;
#pragma unroll
            for (int i = 0; i < 8; i++) {
                float o[8];
                unpk(acc[i][0], o[0], o[1]); unpk(acc[i][1], o[2], o[3]);
                unpk(acc[i][2], o[4], o[5]); unpk(acc[i][3], o[6], o[7]);
                float* cp = pl + (size_t)(mBase + ty * 8 + i) * 256 + uoff + tx * 8;
                *(float4*)(cp)     = make_float4(o[0], o[1], o[2], o[3]);
                *(float4*)(cp + 4) = make_float4(o[4], o[5], o[6], o[7]);
            }

            __syncthreads();                      // all stores issued
            if (tid == 0) { __threadfence(); atomicAdd(&g_chunk_done[c], 1); }
        }
        return;
    }

    // ===================== scan path (R13, proven) =====================
    u64* hbuf = (u64*)smem_raw;                  // [2][2][4][128] u64 = 16KB
    const u32 hb_l = smem_u32(smem_raw);
    const u32 mb_l = hb_l + 16384;               // mbar[4]

    const int w    = tid >> 5;
    const int lane = tid & 31;
    const int j4   = lane >> 3;
    const int ks   = lane & 7;
    const int rank = blockIdx.x;
    const int cg   = blockIdx.y;                 // 0..7
    const int u    = rank * 32 + w * 4 + j4;

    // weights packed along k
    u64 wp[4][16];
#pragma unroll
    for (int m = 0; m < 16; m++) {
        const int kA = ks * 32 + 2 * m;
#pragma unroll
        for (int g = 0; g < 4; g++) {
            wp[g][m] = pk2(Wh[(size_t)kA * 1024 + g * 256 + u],
                           Wh[(size_t)(kA + 1) * 1024 + g * 256 + u]);
        }
    }

    // zero parity-0 buffers of both groups, arm 4 mbarriers
    hbuf[tid] = 0ull; hbuf[tid + 256] = 0ull;          // group 0, parity 0
    hbuf[1024 + tid] = 0ull; hbuf[1024 + tid + 256] = 0ull;  // group 1, parity 0
    if (tid == 0) {
#pragma unroll
        for (int i = 0; i < 4; i++) {
            mbar_init(mb_l + i * 8, 1);
            mbar_expect(mb_l + i * 8, 4096);
        }
    }
    __syncthreads();
    cluster_sync_();

    const int rr = ks & 3;
    const int row0 = cg * 8 + rr;
    const int row1 = cg * 8 + 4 + rr;
    const size_t xE0 = (size_t)row0 * T_SZ * 256 + u;   // plane element offset
    const size_t xE1 = (size_t)row1 * T_SZ * 256 + u;
    const size_t outBase0 = ((size_t)row0 * T_SZ) * H_SZ + u;
    const size_t outBase1 = ((size_t)row1 * T_SZ) * H_SZ + u;

    const int kp  = u >> 1;
    const int mq  = kp & 15;
    const u32 off0 = (u32)(rr * 1024 + ((mq >> 1) * 16 + (kp >> 4) * 2 + (mq & 1)) * 8 + (u & 1) * 4);

    u32 hdst[8], mrem[8];
#pragma unroll
    for (int rk = 0; rk < 8; rk++) {
        hdst[rk] = mapa_sh(hb_l, (u32)rk) + off0;
        mrem[rk] = mapa_sh(mb_l, (u32)rk);
    }

    float c0 = 0.0f, h0 = 0.0f, c1 = 0.0f, h1 = 0.0f;
    u32 ph[4] = {0, 0, 0, 0};

#pragma unroll 1
    for (int t = 0; t < T_SZ; t++) {
        const int b = t & 1;

        // once per 128 steps: wait for the workers' t-chunk
        if ((t & 127) == 0) {
            if (tid == 0) {
                const int* ap = &g_chunk_done[t >> 7];
                int done;
                do {
                    asm volatile("ld.acquire.gpu.b32 %0, [%1];" : "=r"(done) : "l"(ap) : "memory");
                } while (done < 512);
            }
            __syncthreads();
        }

#pragma unroll
        for (int g = 0; g < 2; g++) {
            const u32 moff = (u32)((g * 2 + b) * 8);

            // xg from 4 gate planes — act lanes only, issued before wait
            float xq0 = 0.f, xq1 = 0.f, xq2 = 0.f, xq3 = 0.f;
            if (ks < 4) {
                const float* bp = g_xgp + (g ? xE1 : xE0) + (size_t)t * 256;
                xq0 = __ldg(bp);
                xq1 = __ldg(bp + PLANE);
                xq2 = __ldg(bp + 2 * PLANE);
                xq3 = __ldg(bp + 3 * PLANE);
            }

            if (t > 0) {
                mbar_wait(mb_l + moff, ph[g * 2 + b]);
                ph[g * 2 + b] ^= 1;
            }

            // partial GEMM: 4 rows x 4 gates over 32-k slice
            u64 acc[4][4];
#pragma unroll
            for (int r = 0; r < 4; r++)
#pragma unroll
                for (int gg = 0; gg < 4; gg++) acc[r][gg] = 0ull;

            const u64* hbp = hbuf + (g * 2 + b) * 512;
#pragma unroll
            for (int m2 = 0; m2 < 8; m2++) {
#pragma unroll
                for (int r = 0; r < 4; r++) {
                    ulonglong2 hv = *(const ulonglong2*)(hbp + r * 128 + m2 * 16 + ks * 2);
#pragma unroll
                    for (int gg = 0; gg < 4; gg++) {
                        acc[r][gg] = fma2(hv.x, wp[gg][2 * m2],     acc[r][gg]);
                        acc[r][gg] = fma2(hv.y, wp[gg][2 * m2 + 1], acc[r][gg]);
                    }
                }
            }

            // deferred re-arm for t+2
            if (t > 0 && tid == 0)
                mbar_expect(mb_l + moff, 4096);

            // warp reduce-scatter over ks
            const bool pb = (ks & 1);
            const bool qb = (ks & 2);
            u64 kk[4];
#pragma unroll
            for (int gg = 0; gg < 4; gg++) {
                u64 sA = pb ? acc[0][gg] : acc[1][gg];
                u64 sB = pb ? acc[2][gg] : acc[3][gg];
                u64 rA = __shfl_xor_sync(0xffffffffu, sA, 1);
                u64 rB = __shfl_xor_sync(0xffffffffu, sB, 1);
                u64 k0 = add2(pb ? acc[1][gg] : acc[0][gg], rA);
                u64 k1 = add2(pb ? acc[3][gg] : acc[2][gg], rB);
                u64 s2 = qb ? k0 : k1;
                u64 r2 = __shfl_xor_sync(0xffffffffu, s2, 2);
                u64 kx = add2(qb ? k1 : k0, r2);
                kk[gg] = add2(kx, __shfl_xor_sync(0xffffffffu, kx, 4));
            }

            float hcur = 0.0f;
            if (ks < 4) {
                float e0, e1;
                unpk(kk[0], e0, e1); const float gi  = e0 + e1 + xq0;
                unpk(kk[1], e0, e1); const float gf  = e0 + e1 + xq1;
                unpk(kk[2], e0, e1); const float gg_ = e0 + e1 + xq2;
                unpk(kk[3], e0, e1); const float go  = e0 + e1 + xq3;

                float cv = g ? c1 : c0;
                cv = sigm(gf) * cv + sigm(gi) * tanh_(gg_);
                hcur = sigm(go) * tanh_(cv);
                if (g) { c1 = cv; h1 = hcur; } else { c0 = cv; h0 = hcur; }

                if (t < T_SZ - 1) {
                    const u32 po = (u32)(g * 8192 + (b ^ 1) * 4096);
                    const u32 mo = (u32)((g * 2 + (b ^ 1)) * 8);
#pragma unroll
                    for (int rk = 0; rk < 8; rk++)
                        st_async_f32(hdst[rk] + po, hcur, mrem[rk] + mo);
                }
            }

            // duplicate lanes: fire-and-forget output store
            {
                const float hs = __shfl_xor_sync(0xffffffffu, hcur, 4);
                if (ks >= 4)
                    out[(g ? outBase1 : outBase0) + (size_t)t * H_SZ] = hs;
            }
        }
    }

    // finals: h_T then c_T, each [B, H], appended after Hs
    if (ks < 4) {
        float* fin = out + (size_t)B_SZ * T_SZ * H_SZ;
        fin[(size_t)row0 * H_SZ + u] = h0;
        fin[(size_t)B_SZ * H_SZ + (size_t)row0 * H_SZ + u] = c0;
        fin[(size_t)row1 * H_SZ + u] = h1;
        fin[(size_t)B_SZ * H_SZ + (size_t)row1 * H_SZ + u] = c1;
    }
}

extern "C" void kernel_launch(void* const* d_in, const int* in_sizes, int n_in,
                              void* d_out, int out_size) {
    const float* x    = (const float*)d_in[0];
    const float* W_i  = (const float*)d_in[1];
    const float* W_h  = (const float*)d_in[2];
    const float* bias = (const float*)d_in[3];
    float* out = (float*)d_out;

    reset_ctrs<<<1, 32>>>();

    dim3 grid(8, 17);   // y<8: 8 scan clusters (64 CTAs); y>=8: 72 gemm workers
    fused<<<grid, 256>>>(x, W_i, W_h, bias, out);
}

// round 16
// speedup vs baseline: 1.3452x; 1.1086x over previous
#include <cuda_runtime.h>
#include <cstdint>
#include <cstddef>

typedef unsigned long long u64;
typedef unsigned int u32;

#define B_SZ 64
#define T_SZ 2048
#define H_SZ 256
#define NTILE_TOT 8192   // 16 chunks x 512 tiles (64 rows x 8 n-tiles)

// xg gate-interleaved: g_xgi[m*1024 + u*4 + gate]
__device__ float g_xgi[(size_t)B_SZ * T_SZ * 1024];
__device__ int g_tile_ctr;
__device__ int g_chunk_done[16];

// ---------------- f32x2 helpers ----------------
__device__ __forceinline__ u64 pk2(float lo, float hi) {
    u64 r; asm("mov.b64 %0, {%1, %2};" : "=l"(r) : "f"(lo), "f"(hi)); return r;
}
__device__ __forceinline__ u64 dup2(float a) {
    u64 r; asm("mov.b64 %0, {%1, %1};" : "=l"(r) : "f"(a)); return r;
}
__device__ __forceinline__ u64 fma2(u64 a, u64 b, u64 c) {
    u64 d; asm("fma.rn.f32x2 %0, %1, %2, %3;" : "=l"(d) : "l"(a), "l"(b), "l"(c)); return d;
}
__device__ __forceinline__ u64 add2(u64 a, u64 b) {
    u64 d; asm("add.rn.f32x2 %0, %1, %2;" : "=l"(d) : "l"(a), "l"(b)); return d;
}
__device__ __forceinline__ void unpk(u64 v, float& lo, float& hi) {
    asm("mov.b64 {%0, %1}, %2;" : "=f"(lo), "=f"(hi) : "l"(v));
}

// ---------------- cluster / mbarrier helpers ----------------
__device__ __forceinline__ u32 smem_u32(const void* p) {
    u32 a;
    asm("{ .reg .u64 t; cvta.to.shared.u64 t, %1; cvt.u32.u64 %0, t; }" : "=r"(a) : "l"(p));
    return a;
}
__device__ __forceinline__ u32 mapa_sh(u32 a, u32 rk) {
    u32 r; asm("mapa.shared::cluster.u32 %0, %1, %2;" : "=r"(r) : "r"(a), "r"(rk)); return r;
}
__device__ __forceinline__ void cluster_sync_() {
    asm volatile("barrier.cluster.arrive.aligned;" ::: "memory");
    asm volatile("barrier.cluster.wait.aligned;" ::: "memory");
}
__device__ __forceinline__ void mbar_init(u32 a, u32 cnt) {
    asm volatile("mbarrier.init.shared.b64 [%0], %1;" :: "r"(a), "r"(cnt) : "memory");
}
__device__ __forceinline__ void mbar_expect(u32 a, u32 bytes) {
    asm volatile("mbarrier.arrive.expect_tx.shared.b64 _, [%0], %1;" :: "r"(a), "r"(bytes) : "memory");
}
__device__ __forceinline__ void mbar_wait(u32 a, u32 ph) {
    asm volatile(
        "{\n\t.reg .pred P;\n\t"
        "MW%=:\n\t"
        "mbarrier.try_wait.parity.acquire.cta.shared::cta.b64 P, [%0], %1, 0x989680;\n\t"
        "@!P bra MW%=;\n\t}"
        :: "r"(a), "r"(ph) : "memory");
}
__device__ __forceinline__ void st_async_f32(u32 dst, float v, u32 mb) {
    asm volatile(
        "st.async.shared::cluster.mbarrier::complete_tx::bytes.b32 [%0], %1, [%2];"
        :: "r"(dst), "r"(__float_as_uint(v)), "r"(mb) : "memory");
}

// ---------------- activations ----------------
__device__ __forceinline__ float sigm(float x) {
    return __fdividef(1.0f, 1.0f + __expf(-x));
}
__device__ __forceinline__ float tanh_(float x) {
    return 1.0f - __fdividef(2.0f, __expf(2.0f * x) + 1.0f);
}

__global__ void reset_ctrs() {
    if (threadIdx.x == 0) g_tile_ctr = 0;
    if (threadIdx.x < 16) g_chunk_done[threadIdx.x] = 0;
}

// =====================================================================
// Fused kernel. Grid (8,17), cluster (8,1,1).
//  y < 8 : scan clusters (R13-proven, reads g_xgi float4/owner)
//  y >= 8: 72 worker CTAs, persistent gemm in t-chunk-major order.
//    Tile = 128 m-rows x (32 units x 4 gates). Split smem arrays
//    (stride-4 vectors) kill the 4-way LDS bank conflicts; epilogue
//    writes gate-interleaved g_xgi contiguously (repack eliminated).
// =====================================================================
__global__ __launch_bounds__(256, 1) __cluster_dims__(8, 1, 1)
void fused(const float* __restrict__ x, const float* __restrict__ Wi,
           const float* __restrict__ Wh, const float* __restrict__ bias,
           float* __restrict__ out)
{
    __shared__ __align__(16) char smem_raw[32800];
    const int tid = threadIdx.x;

    if (blockIdx.y >= 8) {
        // ===================== worker path (gemm) =====================
        // split arrays: [2][16][64] floats each (8KB each)
        float (*As0)[16][64] = (float(*)[16][64])(smem_raw);
        float (*As1)[16][64] = (float(*)[16][64])(smem_raw + 8192);
        float (*Bs0)[16][64] = (float(*)[16][64])(smem_raw + 16384);
        float (*Bs1)[16][64] = (float(*)[16][64])(smem_raw + 24576);
        int* s_task = (int*)(smem_raw + 32768);

        const int tx = tid & 15;
        const int ty = tid >> 4;
        // A loads: 2 float4 along k per thread
        const int arow0 = tid >> 2,         akq0 = tid & 3;
        const int arow1 = (tid + 256) >> 2, akq1 = (tid + 256) & 3;
        const int aw0 = (arow0 >> 3) * 4 + (arow0 & 3);
        const int aw1 = (arow1 >> 3) * 4 + (arow1 & 3);
        const bool asel0 = ((arow0 >> 2) & 1) != 0;   // true -> As1
        const bool asel1 = ((arow1 >> 2) & 1) != 0;
        // B loads: lane -> (gate, quad)
        const int bk0 = tid >> 5,  g0 = (tid & 31) >> 3, q0 = tid & 7;
        const int bk1 = bk0 + 8;

        for (;;) {
            __syncthreads();
            if (tid == 0) *s_task = atomicAdd(&g_tile_ctr, 1);
            __syncthreads();
            const int task = *s_task;
            if (task >= NTILE_TOT) break;
            const int c     = task >> 9;          // t-chunk 0..15
            const int rem   = task & 511;
            const int row   = rem >> 3;           // batch row 0..63
            const int nt    = rem & 7;            // n-tile (32 units)
            const int mBase = row * 2048 + c * 128;
            const int uBase = nt * 32;

            // bias init: cols j = tx*8..+7 -> u0 = uBase+2tx (g0..3), u0+1 (g0..3)
            u64 acc[8][4];
            {
                const int u0 = uBase + tx * 2;
                u64 b0 = pk2(bias[u0],       bias[256 + u0]);
                u64 b1 = pk2(bias[512 + u0], bias[768 + u0]);
                u64 b2 = pk2(bias[u0 + 1],       bias[256 + u0 + 1]);
                u64 b3 = pk2(bias[512 + u0 + 1], bias[768 + u0 + 1]);
#pragma unroll
                for (int i = 0; i < 8; i++) { acc[i][0] = b0; acc[i][1] = b1; acc[i][2] = b2; acc[i][3] = b3; }
            }

            float4 a_r0, a_r1, b_r0, b_r1;
            // prologue chunk 0
            a_r0 = *(const float4*)(x + (size_t)(mBase + arow0) * 256 + akq0 * 4);
            a_r1 = *(const float4*)(x + (size_t)(mBase + arow1) * 256 + akq1 * 4);
            b_r0 = *(const float4*)(Wi + (size_t)bk0 * 1024 + g0 * 256 + uBase + q0 * 4);
            b_r1 = *(const float4*)(Wi + (size_t)bk1 * 1024 + g0 * 256 + uBase + q0 * 4);
            {
                float* a0d = asel0 ? &As1[0][0][0] : &As0[0][0][0];
                float* a1d = asel1 ? &As1[0][0][0] : &As0[0][0][0];
                a0d[(akq0 * 4 + 0) * 64 + aw0] = a_r0.x; a0d[(akq0 * 4 + 1) * 64 + aw0] = a_r0.y;
                a0d[(akq0 * 4 + 2) * 64 + aw0] = a_r0.z; a0d[(akq0 * 4 + 3) * 64 + aw0] = a_r0.w;
                a1d[(akq1 * 4 + 0) * 64 + aw1] = a_r1.x; a1d[(akq1 * 4 + 1) * 64 + aw1] = a_r1.y;
                a1d[(akq1 * 4 + 2) * 64 + aw1] = a_r1.z; a1d[(akq1 * 4 + 3) * 64 + aw1] = a_r1.w;
                Bs0[0][bk0][8 * q0 + g0] = b_r0.x;     Bs1[0][bk0][8 * q0 + g0] = b_r0.y;
                Bs0[0][bk0][8 * q0 + 4 + g0] = b_r0.z; Bs1[0][bk0][8 * q0 + 4 + g0] = b_r0.w;
                Bs0[0][bk1 - 8][0] = Bs0[0][bk1 - 8][0]; // no-op placeholder removed below
            }
            // second B half (k 8..15)
            Bs0[0][bk1][8 * q0 + g0] = b_r1.x;     Bs1[0][bk1][8 * q0 + g0] = b_r1.y;
            Bs0[0][bk1][8 * q0 + 4 + g0] = b_r1.z; Bs1[0][bk1][8 * q0 + 4 + g0] = b_r1.w;
            __syncthreads();

            int p = 0;
#pragma unroll 1
            for (int kc = 0; kc < 16; kc++) {
                if (kc < 15) {
                    const int kb = (kc + 1) * 16;
                    a_r0 = *(const float4*)(x + (size_t)(mBase + arow0) * 256 + kb + akq0 * 4);
                    a_r1 = *(const float4*)(x + (size_t)(mBase + arow1) * 256 + kb + akq1 * 4);
                    b_r0 = *(const float4*)(Wi + (size_t)(kb + bk0) * 1024 + g0 * 256 + uBase + q0 * 4);
                    b_r1 = *(const float4*)(Wi + (size_t)(kb + bk1) * 1024 + g0 * 256 + uBase + q0 * 4);
                }
#pragma unroll
                for (int k = 0; k < 16; k++) {
                    float4 a0 = *(float4*)&As0[p][k][ty * 4];   // rows ty*8+0..3
                    float4 a1 = *(float4*)&As1[p][k][ty * 4];   // rows ty*8+4..7
                    float4 b0 = *(float4*)&Bs0[p][k][tx * 4];   // cols tx*8+0..3
                    float4 b1 = *(float4*)&Bs1[p][k][tx * 4];   // cols tx*8+4..7
                    u64 bb0 = pk2(b0.x, b0.y), bb1 = pk2(b0.z, b0.w);
                    u64 bb2 = pk2(b1.x, b1.y), bb3 = pk2(b1.z, b1.w);
                    float aa[8] = {a0.x, a0.y, a0.z, a0.w, a1.x, a1.y, a1.z, a1.w};
#pragma unroll
                    for (int i = 0; i < 8; i++) {
                        u64 ad = dup2(aa[i]);
                        acc[i][0] = fma2(ad, bb0, acc[i][0]);
                        acc[i][1] = fma2(ad, bb1, acc[i][1]);
                        acc[i][2] = fma2(ad, bb2, acc[i][2]);
                        acc[i][3] = fma2(ad, bb3, acc[i][3]);
                    }
                }
                if (kc < 15) {
                    const int pn = p ^ 1;
                    float* a0d = asel0 ? &As1[pn][0][0] : &As0[pn][0][0];
                    float* a1d = asel1 ? &As1[pn][0][0] : &As0[pn][0][0];
                    a0d[(akq0 * 4 + 0) * 64 + aw0] = a_r0.x; a0d[(akq0 * 4 + 1) * 64 + aw0] = a_r0.y;
                    a0d[(akq0 * 4 + 2) * 64 + aw0] = a_r0.z; a0d[(akq0 * 4 + 3) * 64 + aw0] = a_r0.w;
                    a1d[(akq1 * 4 + 0) * 64 + aw1] = a_r1.x; a1d[(akq1 * 4 + 1) * 64 + aw1] = a_r1.y;
                    a1d[(akq1 * 4 + 2) * 64 + aw1] = a_r1.z; a1d[(akq1 * 4 + 3) * 64 + aw1] = a_r1.w;
                    Bs0[pn][bk0][8 * q0 + g0] = b_r0.x;     Bs1[pn][bk0][8 * q0 + g0] = b_r0.y;
                    Bs0[pn][bk0][8 * q0 + 4 + g0] = b_r0.z; Bs1[pn][bk0][8 * q0 + 4 + g0] = b_r0.w;
                    Bs0[pn][bk1][8 * q0 + g0] = b_r1.x;     Bs1[pn][bk1][8 * q0 + g0] = b_r1.y;
                    Bs0[pn][bk1][8 * q0 + 4 + g0] = b_r1.z; Bs1[pn][bk1][8 * q0 + 4 + g0] = b_r1.w;
                    __syncthreads();
                    p = pn;
                }
            }

            // epilogue: gate-interleaved, fully contiguous
#pragma unroll
            for (int i = 0; i < 8; i++) {
                float o[8];
                unpk(acc[i][0], o[0], o[1]); unpk(acc[i][1], o[2], o[3]);
                unpk(acc[i][2], o[4], o[5]); unpk(acc[i][3], o[6], o[7]);
                float* cp = g_xgi + (size_t)(mBase + ty * 8 + i) * 1024 + nt * 128 + tx * 8;
                *(float4*)(cp)     = make_float4(o[0], o[1], o[2], o[3]);
                *(float4*)(cp + 4) = make_float4(o[4], o[5], o[6], o[7]);
            }

            __syncthreads();
            if (tid == 0) { __threadfence(); atomicAdd(&g_chunk_done[c], 1); }
        }
        return;
    }

    // ===================== scan path (R13, proven) =====================
    u64* hbuf = (u64*)smem_raw;                  // [2][2][4][128] u64 = 16KB
    const u32 hb_l = smem_u32(smem_raw);
    const u32 mb_l = hb_l + 16384;               // mbar[4]

    const int w    = tid >> 5;
    const int lane = tid & 31;
    const int j4   = lane >> 3;
    const int ks   = lane & 7;
    const int rank = blockIdx.x;
    const int cg   = blockIdx.y;                 // 0..7
    const int u    = rank * 32 + w * 4 + j4;

    u64 wp[4][16];
#pragma unroll
    for (int m = 0; m < 16; m++) {
        const int kA = ks * 32 + 2 * m;
#pragma unroll
        for (int g = 0; g < 4; g++) {
            wp[g][m] = pk2(Wh[(size_t)kA * 1024 + g * 256 + u],
                           Wh[(size_t)(kA + 1) * 1024 + g * 256 + u]);
        }
    }

    hbuf[tid] = 0ull; hbuf[tid + 256] = 0ull;
    hbuf[1024 + tid] = 0ull; hbuf[1024 + tid + 256] = 0ull;
    if (tid == 0) {
#pragma unroll
        for (int i = 0; i < 4; i++) {
            mbar_init(mb_l + i * 8, 1);
            mbar_expect(mb_l + i * 8, 4096);
        }
    }
    __syncthreads();
    cluster_sync_();

    const int rr = ks & 3;
    const int row0 = cg * 8 + rr;
    const int row1 = cg * 8 + 4 + rr;
    const size_t xgBase0  = ((size_t)row0 * T_SZ) * 1024 + (size_t)u * 4;
    const size_t xgBase1  = ((size_t)row1 * T_SZ) * 1024 + (size_t)u * 4;
    const size_t outBase0 = ((size_t)row0 * T_SZ) * H_SZ + u;
    const size_t outBase1 = ((size_t)row1 * T_SZ) * H_SZ + u;

    const int kp  = u >> 1;
    const int mq  = kp & 15;
    const u32 off0 = (u32)(rr * 1024 + ((mq >> 1) * 16 + (kp >> 4) * 2 + (mq & 1)) * 8 + (u & 1) * 4);

    u32 hdst[8], mrem[8];
#pragma unroll
    for (int rk = 0; rk < 8; rk++) {
        hdst[rk] = mapa_sh(hb_l, (u32)rk) + off0;
        mrem[rk] = mapa_sh(mb_l, (u32)rk);
    }

    float c0 = 0.0f, h0 = 0.0f, c1 = 0.0f, h1 = 0.0f;
    u32 ph[4] = {0, 0, 0, 0};

#pragma unroll 1
    for (int t = 0; t < T_SZ; t++) {
        const int b = t & 1;

        if ((t & 127) == 0) {     // wait for workers' t-chunk
            if (tid == 0) {
                const int* ap = &g_chunk_done[t >> 7];
                int done;
                do {
                    asm volatile("ld.acquire.gpu.b32 %0, [%1];" : "=r"(done) : "l"(ap) : "memory");
                } while (done < 512);
            }
            __syncthreads();
        }

#pragma unroll
        for (int g = 0; g < 2; g++) {
            const u32 moff = (u32)((g * 2 + b) * 8);

            float4 xq = make_float4(0.f, 0.f, 0.f, 0.f);
            if (ks < 4)
                xq = *(const float4*)(g_xgi + (g ? xgBase1 : xgBase0) + (size_t)t * 1024);

            if (t > 0) {
                mbar_wait(mb_l + moff, ph[g * 2 + b]);
                ph[g * 2 + b] ^= 1;
            }

            u64 acc[4][4];
#pragma unroll
            for (int r = 0; r < 4; r++)
#pragma unroll
                for (int gg = 0; gg < 4; gg++) acc[r][gg] = 0ull;

            const u64* hbp = hbuf + (g * 2 + b) * 512;
#pragma unroll
            for (int m2 = 0; m2 < 8; m2++) {
#pragma unroll
                for (int r = 0; r < 4; r++) {
                    ulonglong2 hv = *(const ulonglong2*)(hbp + r * 128 + m2 * 16 + ks * 2);
#pragma unroll
                    for (int gg = 0; gg < 4; gg++) {
                        acc[r][gg] = fma2(hv.x, wp[gg][2 * m2],     acc[r][gg]);
                        acc[r][gg] = fma2(hv.y, wp[gg][2 * m2 + 1], acc[r][gg]);
                    }
                }
            }

            if (t > 0 && tid == 0)
                mbar_expect(mb_l + moff, 4096);

            const bool pb = (ks & 1);
            const bool qb = (ks & 2);
            u64 kk[4];
#pragma unroll
            for (int gg = 0; gg < 4; gg++) {
                u64 sA = pb ? acc[0][gg] : acc[1][gg];
                u64 sB = pb ? acc[2][gg] : acc[3][gg];
                u64 rA = __shfl_xor_sync(0xffffffffu, sA, 1);
                u64 rB = __shfl_xor_sync(0xffffffffu, sB, 1);
                u64 k0 = add2(pb ? acc[1][gg] : acc[0][gg], rA);
                u64 k1 = add2(pb ? acc[3][gg] : acc[2][gg], rB);
                u64 s2 = qb ? k0 : k1;
                u64 r2 = __shfl_xor_sync(0xffffffffu, s2, 2);
                u64 kx = add2(qb ? k1 : k0, r2);
                kk[gg] = add2(kx, __shfl_xor_sync(0xffffffffu, kx, 4));
            }

            float hcur = 0.0f;
            if (ks < 4) {
                float e0, e1;
                unpk(kk[0], e0, e1); const float gi  = e0 + e1 + xq.x;
                unpk(kk[1], e0, e1); const float gf  = e0 + e1 + xq.y;
                unpk(kk[2], e0, e1); const float gg_ = e0 + e1 + xq.z;
                unpk(kk[3], e0, e1); const float go  = e0 + e1 + xq.w;

                float cv = g ? c1 : c0;
                cv = sigm(gf) * cv + sigm(gi) * tanh_(gg_);
                hcur = sigm(go) * tanh_(cv);
                if (g) { c1 = cv; h1 = hcur; } else { c0 = cv; h0 = hcur; }

                if (t < T_SZ - 1) {
                    const u32 po = (u32)(g * 8192 + (b ^ 1) * 4096);
                    const u32 mo = (u32)((g * 2 + (b ^ 1)) * 8);
#pragma unroll
                    for (int rk = 0; rk < 8; rk++)
                        st_async_f32(hdst[rk] + po, hcur, mrem[rk] + mo);
                }
            }

            {
                const float hs = __shfl_xor_sync(0xffffffffu, hcur, 4);
                if (ks >= 4)
                    out[(g ? outBase1 : outBase0) + (size_t)t * H_SZ] = hs;
            }
        }
    }

    if (ks < 4) {
        float* fin = out + (size_t)B_SZ * T_SZ * H_SZ;
        fin[(size_t)row0 * H_SZ + u] = h0;
        fin[(size_t)B_SZ * H_SZ + (size_t)row0 * H_SZ + u] = c0;
        fin[(size_t)row1 * H_SZ + u] = h1;
        fin[(size_t)B_SZ * H_SZ + (size_t)row1 * H_SZ + u] = c1;
    }
}

extern "C" void kernel_launch(void* const* d_in, const int* in_sizes, int n_in,
                              void* d_out, int out_size) {
    const float* x    = (const float*)d_in[0];
    const float* W_i  = (const float*)d_in[1];
    const float* W_h  = (const float*)d_in[2];
    const float* bias = (const float*)d_in[3];
    float* out = (float*)d_out;

    reset_ctrs<<<1, 32>>>();

    dim3 grid(8, 17);   // y<8: 8 scan clusters (64 CTAs); y>=8: 72 gemm workers
    fused<<<grid, 256>>>(x, W_i, W_h, bias, out);
}

// round 17
// speedup vs baseline: 1.3567x; 1.0085x over previous
#include <cuda_runtime.h>
#include <cstdint>
#include <cstddef>

typedef unsigned long long u64;
typedef unsigned int u32;

#define B_SZ 64
#define T_SZ 2048
#define H_SZ 256
#define NTASK 4096      // 16 chunks x 64 rows x 4 nt-pairs
#define TASKS_PER_CHUNK 256

// xg gate-interleaved: g_xgi[m*1024 + u*4 + gate]
__device__ float g_xgi[(size_t)B_SZ * T_SZ * 1024];
__device__ int g_tile_ctr;
__device__ int g_chunk_done[16];

// ---------------- f32x2 helpers ----------------
__device__ __forceinline__ u64 pk2(float lo, float hi) {
    u64 r; asm("mov.b64 %0, {%1, %2};" : "=l"(r) : "f"(lo), "f"(hi)); return r;
}
__device__ __forceinline__ u64 dup2(float a) {
    u64 r; asm("mov.b64 %0, {%1, %1};" : "=l"(r) : "f"(a)); return r;
}
__device__ __forceinline__ u64 fma2(u64 a, u64 b, u64 c) {
    u64 d; asm("fma.rn.f32x2 %0, %1, %2, %3;" : "=l"(d) : "l"(a), "l"(b), "l"(c)); return d;
}
__device__ __forceinline__ u64 add2(u64 a, u64 b) {
    u64 d; asm("add.rn.f32x2 %0, %1, %2;" : "=l"(d) : "l"(a), "l"(b)); return d;
}
__device__ __forceinline__ void unpk(u64 v, float& lo, float& hi) {
    asm("mov.b64 {%0, %1}, %2;" : "=f"(lo), "=f"(hi) : "l"(v));
}

// ---------------- cluster / mbarrier helpers ----------------
__device__ __forceinline__ u32 smem_u32(const void* p) {
    u32 a;
    asm("{ .reg .u64 t; cvta.to.shared.u64 t, %1; cvt.u32.u64 %0, t; }" : "=r"(a) : "l"(p));
    return a;
}
__device__ __forceinline__ u32 mapa_sh(u32 a, u32 rk) {
    u32 r; asm("mapa.shared::cluster.u32 %0, %1, %2;" : "=r"(r) : "r"(a), "r"(rk)); return r;
}
__device__ __forceinline__ void cluster_sync_() {
    asm volatile("barrier.cluster.arrive.aligned;" ::: "memory");
    asm volatile("barrier.cluster.wait.aligned;" ::: "memory");
}
__device__ __forceinline__ void mbar_init(u32 a, u32 cnt) {
    asm volatile("mbarrier.init.shared.b64 [%0], %1;" :: "r"(a), "r"(cnt) : "memory");
}
__device__ __forceinline__ void mbar_expect(u32 a, u32 bytes) {
    asm volatile("mbarrier.arrive.expect_tx.shared.b64 _, [%0], %1;" :: "r"(a), "r"(bytes) : "memory");
}
__device__ __forceinline__ void mbar_wait(u32 a, u32 ph) {
    asm volatile(
        "{\n\t.reg .pred P;\n\t"
        "MW%=:\n\t"
        "mbarrier.try_wait.parity.acquire.cta.shared::cta.b64 P, [%0], %1, 0x989680;\n\t"
        "@!P bra MW%=;\n\t}"
        :: "r"(a), "r"(ph) : "memory");
}
__device__ __forceinline__ void st_async_f32(u32 dst, float v, u32 mb) {
    asm volatile(
        "st.async.shared::cluster.mbarrier::complete_tx::bytes.b32 [%0], %1, [%2];"
        :: "r"(dst), "r"(__float_as_uint(v)), "r"(mb) : "memory");
}

// ---------------- activations ----------------
__device__ __forceinline__ float sigm(float x) {
    return __fdividef(1.0f, 1.0f + __expf(-x));
}
__device__ __forceinline__ float tanh_(float x) {
    return 1.0f - __fdividef(2.0f, __expf(2.0f * x) + 1.0f);
}

__global__ void reset_ctrs() {
    if (threadIdx.x == 0) g_tile_ctr = 0;
    if (threadIdx.x < 16) g_chunk_done[threadIdx.x] = 0;
}

// =====================================================================
// Fused kernel. Grid (8,17), cluster (8,1,1), dynamic smem 49280B.
//  y < 8 : scan clusters (R13-proven, reads g_xgi float4/owner)
//  y >= 8: 72 worker CTAs; task = 128 m-rows x TWO n-tiles sharing A.
//    Two independent accumulator sets (128 regs) give each warp 64
//    fma2 per k -> fma-pipe-bound even at 1 CTA/SM.
// =====================================================================
__global__ __launch_bounds__(256, 1) __cluster_dims__(8, 1, 1)
void fused(const float* __restrict__ x, const float* __restrict__ Wi,
           const float* __restrict__ Wh, const float* __restrict__ bias,
           float* __restrict__ out)
{
    extern __shared__ __align__(16) char smem_raw[];
    const int tid = threadIdx.x;

    if (blockIdx.y >= 8) {
        // ===================== worker path (gemm, 2 n-tiles) =====================
        float (*As0)[16][64]  = (float(*)[16][64])(smem_raw);             // rows 0-3 of each 8-group
        float (*As1)[16][64]  = (float(*)[16][64])(smem_raw + 8192);      // rows 4-7
        float (*B0s0)[16][64] = (float(*)[16][64])(smem_raw + 16384);     // tile0 cols 0-3 of each 8
        float (*B0s1)[16][64] = (float(*)[16][64])(smem_raw + 24576);
        float (*B1s0)[16][64] = (float(*)[16][64])(smem_raw + 32768);     // tile1
        float (*B1s1)[16][64] = (float(*)[16][64])(smem_raw + 40960);
        int* s_task = (int*)(smem_raw + 49152);

        const int tx = tid & 15;
        const int ty = tid >> 4;
        const int arow0 = tid >> 2,         akq0 = tid & 3;
        const int arow1 = (tid + 256) >> 2, akq1 = (tid + 256) & 3;
        const int aw0 = (arow0 >> 3) * 4 + (arow0 & 3);
        const int aw1 = (arow1 >> 3) * 4 + (arow1 & 3);
        const bool asel0 = ((arow0 >> 2) & 1) != 0;
        const bool asel1 = ((arow1 >> 2) & 1) != 0;
        const int bk0 = tid >> 5, g0 = (tid & 31) >> 3, q0 = tid & 7;
        const int bk1 = bk0 + 8;

        for (;;) {
            __syncthreads();
            if (tid == 0) *s_task = atomicAdd(&g_tile_ctr, 1);
            __syncthreads();
            const int task = *s_task;
            if (task >= NTASK) break;
            const int c     = task >> 8;          // t-chunk 0..15
            const int rem   = task & 255;
            const int row   = rem >> 2;           // batch row 0..63
            const int np    = rem & 3;            // nt-pair 0..3
            const int mBase = row * 2048 + c * 128;
            const int uB0   = np * 64;            // tile0 units
            const int uB1   = np * 64 + 32;       // tile1 units

            u64 accA[8][4], accB[8][4];
            {
                const int ua = uB0 + tx * 2, ub = uB1 + tx * 2;
                u64 a0 = pk2(bias[ua],       bias[256 + ua]);
                u64 a1 = pk2(bias[512 + ua], bias[768 + ua]);
                u64 a2 = pk2(bias[ua + 1],       bias[256 + ua + 1]);
                u64 a3 = pk2(bias[512 + ua + 1], bias[768 + ua + 1]);
                u64 b0 = pk2(bias[ub],       bias[256 + ub]);
                u64 b1 = pk2(bias[512 + ub], bias[768 + ub]);
                u64 b2 = pk2(bias[ub + 1],       bias[256 + ub + 1]);
                u64 b3 = pk2(bias[512 + ub + 1], bias[768 + ub + 1]);
#pragma unroll
                for (int i = 0; i < 8; i++) {
                    accA[i][0] = a0; accA[i][1] = a1; accA[i][2] = a2; accA[i][3] = a3;
                    accB[i][0] = b0; accB[i][1] = b1; accB[i][2] = b2; accB[i][3] = b3;
                }
            }

            float4 a_r0, a_r1, bra0, bra1, brb0, brb1;
            a_r0 = *(const float4*)(x + (size_t)(mBase + arow0) * 256 + akq0 * 4);
            a_r1 = *(const float4*)(x + (size_t)(mBase + arow1) * 256 + akq1 * 4);
            bra0 = *(const float4*)(Wi + (size_t)bk0 * 1024 + g0 * 256 + uB0 + q0 * 4);
            bra1 = *(const float4*)(Wi + (size_t)bk1 * 1024 + g0 * 256 + uB0 + q0 * 4);
            brb0 = *(const float4*)(Wi + (size_t)bk0 * 1024 + g0 * 256 + uB1 + q0 * 4);
            brb1 = *(const float4*)(Wi + (size_t)bk1 * 1024 + g0 * 256 + uB1 + q0 * 4);
            {
                float* a0d = asel0 ? &As1[0][0][0] : &As0[0][0][0];
                float* a1d = asel1 ? &As1[0][0][0] : &As0[0][0][0];
                a0d[(akq0 * 4 + 0) * 64 + aw0] = a_r0.x; a0d[(akq0 * 4 + 1) * 64 + aw0] = a_r0.y;
                a0d[(akq0 * 4 + 2) * 64 + aw0] = a_r0.z; a0d[(akq0 * 4 + 3) * 64 + aw0] = a_r0.w;
                a1d[(akq1 * 4 + 0) * 64 + aw1] = a_r1.x; a1d[(akq1 * 4 + 1) * 64 + aw1] = a_r1.y;
                a1d[(akq1 * 4 + 2) * 64 + aw1] = a_r1.z; a1d[(akq1 * 4 + 3) * 64 + aw1] = a_r1.w;
                B0s0[0][bk0][8 * q0 + g0] = bra0.x;     B0s1[0][bk0][8 * q0 + g0] = bra0.y;
                B0s0[0][bk0][8 * q0 + 4 + g0] = bra0.z; B0s1[0][bk0][8 * q0 + 4 + g0] = bra0.w;
                B0s0[0][bk1][8 * q0 + g0] = bra1.x;     B0s1[0][bk1][8 * q0 + g0] = bra1.y;
                B0s0[0][bk1][8 * q0 + 4 + g0] = bra1.z; B0s1[0][bk1][8 * q0 + 4 + g0] = bra1.w;
                B1s0[0][bk0][8 * q0 + g0] = brb0.x;     B1s1[0][bk0][8 * q0 + g0] = brb0.y;
                B1s0[0][bk0][8 * q0 + 4 + g0] = brb0.z; B1s1[0][bk0][8 * q0 + 4 + g0] = brb0.w;
                B1s0[0][bk1][8 * q0 + g0] = brb1.x;     B1s1[0][bk1][8 * q0 + g0] = brb1.y;
                B1s0[0][bk1][8 * q0 + 4 + g0] = brb1.z; B1s1[0][bk1][8 * q0 + 4 + g0] = brb1.w;
            }
            __syncthreads();

            int p = 0;
#pragma unroll 1
            for (int kc = 0; kc < 16; kc++) {
                if (kc < 15) {
                    const int kb = (kc + 1) * 16;
                    a_r0 = *(const float4*)(x + (size_t)(mBase + arow0) * 256 + kb + akq0 * 4);
                    a_r1 = *(const float4*)(x + (size_t)(mBase + arow1) * 256 + kb + akq1 * 4);
                    bra0 = *(const float4*)(Wi + (size_t)(kb + bk0) * 1024 + g0 * 256 + uB0 + q0 * 4);
                    bra1 = *(const float4*)(Wi + (size_t)(kb + bk1) * 1024 + g0 * 256 + uB0 + q0 * 4);
                    brb0 = *(const float4*)(Wi + (size_t)(kb + bk0) * 1024 + g0 * 256 + uB1 + q0 * 4);
                    brb1 = *(const float4*)(Wi + (size_t)(kb + bk1) * 1024 + g0 * 256 + uB1 + q0 * 4);
                }
#pragma unroll
                for (int k = 0; k < 16; k++) {
                    float4 a0 = *(float4*)&As0[p][k][ty * 4];
                    float4 a1 = *(float4*)&As1[p][k][ty * 4];
                    float4 ba0 = *(float4*)&B0s0[p][k][tx * 4];
                    float4 ba1 = *(float4*)&B0s1[p][k][tx * 4];
                    float4 bb0 = *(float4*)&B1s0[p][k][tx * 4];
                    float4 bb1 = *(float4*)&B1s1[p][k][tx * 4];
                    u64 pa0 = pk2(ba0.x, ba0.y), pa1 = pk2(ba0.z, ba0.w);
                    u64 pa2 = pk2(ba1.x, ba1.y), pa3 = pk2(ba1.z, ba1.w);
                    u64 pb0 = pk2(bb0.x, bb0.y), pb1 = pk2(bb0.z, bb0.w);
                    u64 pb2 = pk2(bb1.x, bb1.y), pb3 = pk2(bb1.z, bb1.w);
                    float aa[8] = {a0.x, a0.y, a0.z, a0.w, a1.x, a1.y, a1.z, a1.w};
#pragma unroll
                    for (int i = 0; i < 8; i++) {
                        u64 ad = dup2(aa[i]);
                        accA[i][0] = fma2(ad, pa0, accA[i][0]);
                        accA[i][1] = fma2(ad, pa1, accA[i][1]);
                        accA[i][2] = fma2(ad, pa2, accA[i][2]);
                        accA[i][3] = fma2(ad, pa3, accA[i][3]);
                        accB[i][0] = fma2(ad, pb0, accB[i][0]);
                        accB[i][1] = fma2(ad, pb1, accB[i][1]);
                        accB[i][2] = fma2(ad, pb2, accB[i][2]);
                        accB[i][3] = fma2(ad, pb3, accB[i][3]);
                    }
                }
                if (kc < 15) {
                    const int pn = p ^ 1;
                    float* a0d = asel0 ? &As1[pn][0][0] : &As0[pn][0][0];
                    float* a1d = asel1 ? &As1[pn][0][0] : &As0[pn][0][0];
                    a0d[(akq0 * 4 + 0) * 64 + aw0] = a_r0.x; a0d[(akq0 * 4 + 1) * 64 + aw0] = a_r0.y;
                    a0d[(akq0 * 4 + 2) * 64 + aw0] = a_r0.z; a0d[(akq0 * 4 + 3) * 64 + aw0] = a_r0.w;
                    a1d[(akq1 * 4 + 0) * 64 + aw1] = a_r1.x; a1d[(akq1 * 4 + 1) * 64 + aw1] = a_r1.y;
                    a1d[(akq1 * 4 + 2) * 64 + aw1] = a_r1.z; a1d[(akq1 * 4 + 3) * 64 + aw1] = a_r1.w;
                    B0s0[pn][bk0][8 * q0 + g0] = bra0.x;     B0s1[pn][bk0][8 * q0 + g0] = bra0.y;
                    B0s0[pn][bk0][8 * q0 + 4 + g0] = bra0.z; B0s1[pn][bk0][8 * q0 + 4 + g0] = bra0.w;
                    B0s0[pn][bk1][8 * q0 + g0] = bra1.x;     B0s1[pn][bk1][8 * q0 + g0] = bra1.y;
                    B0s0[pn][bk1][8 * q0 + 4 + g0] = bra1.z; B0s1[pn][bk1][8 * q0 + 4 + g0] = bra1.w;
                    B1s0[pn][bk0][8 * q0 + g0] = brb0.x;     B1s1[pn][bk0][8 * q0 + g0] = brb0.y;
                    B1s0[pn][bk0][8 * q0 + 4 + g0] = brb0.z; B1s1[pn][bk0][8 * q0 + 4 + g0] = brb0.w;
                    B1s0[pn][bk1][8 * q0 + g0] = brb1.x;     B1s1[pn][bk1][8 * q0 + g0] = brb1.y;
                    B1s0[pn][bk1][8 * q0 + 4 + g0] = brb1.z; B1s1[pn][bk1][8 * q0 + 4 + g0] = brb1.w;
                    __syncthreads();
                    p = pn;
                }
            }

            // epilogue: gate-interleaved, contiguous (both tiles)
#pragma unroll
            for (int i = 0; i < 8; i++) {
                float o[8];
                unpk(accA[i][0], o[0], o[1]); unpk(accA[i][1], o[2], o[3]);
                unpk(accA[i][2], o[4], o[5]); unpk(accA[i][3], o[6], o[7]);
                float* cp = g_xgi + (size_t)(mBase + ty * 8 + i) * 1024 + np * 256 + tx * 8;
                *(float4*)(cp)     = make_float4(o[0], o[1], o[2], o[3]);
                *(float4*)(cp + 4) = make_float4(o[4], o[5], o[6], o[7]);
                unpk(accB[i][0], o[0], o[1]); unpk(accB[i][1], o[2], o[3]);
                unpk(accB[i][2], o[4], o[5]); unpk(accB[i][3], o[6], o[7]);
                float* cq = cp + 128;
                *(float4*)(cq)     = make_float4(o[0], o[1], o[2], o[3]);
                *(float4*)(cq + 4) = make_float4(o[4], o[5], o[6], o[7]);
            }

            __syncthreads();
            if (tid == 0) { __threadfence(); atomicAdd(&g_chunk_done[c], 1); }
        }
        return;
    }

    // ===================== scan path (R13, proven) =====================
    u64* hbuf = (u64*)smem_raw;                  // [2][2][4][128] u64 = 16KB
    const u32 hb_l = smem_u32(smem_raw);
    const u32 mb_l = hb_l + 16384;               // mbar[4]

    const int w    = tid >> 5;
    const int lane = tid & 31;
    const int j4   = lane >> 3;
    const int ks   = lane & 7;
    const int rank = blockIdx.x;
    const int cg   = blockIdx.y;                 // 0..7
    const int u    = rank * 32 + w * 4 + j4;

    u64 wp[4][16];
#pragma unroll
    for (int m = 0; m < 16; m++) {
        const int kA = ks * 32 + 2 * m;
#pragma unroll
        for (int g = 0; g < 4; g++) {
            wp[g][m] = pk2(Wh[(size_t)kA * 1024 + g * 256 + u],
                           Wh[(size_t)(kA + 1) * 1024 + g * 256 + u]);
        }
    }

    hbuf[tid] = 0ull; hbuf[tid + 256] = 0ull;
    hbuf[1024 + tid] = 0ull; hbuf[1024 + tid + 256] = 0ull;
    if (tid == 0) {
#pragma unroll
        for (int i = 0; i < 4; i++) {
            mbar_init(mb_l + i * 8, 1);
            mbar_expect(mb_l + i * 8, 4096);
        }
    }
    __syncthreads();
    cluster_sync_();

    const int rr = ks & 3;
    const int row0 = cg * 8 + rr;
    const int row1 = cg * 8 + 4 + rr;
    const size_t xgBase0  = ((size_t)row0 * T_SZ) * 1024 + (size_t)u * 4;
    const size_t xgBase1  = ((size_t)row1 * T_SZ) * 1024 + (size_t)u * 4;
    const size_t outBase0 = ((size_t)row0 * T_SZ) * H_SZ + u;
    const size_t outBase1 = ((size_t)row1 * T_SZ) * H_SZ + u;

    const int kp  = u >> 1;
    const int mq  = kp & 15;
    const u32 off0 = (u32)(rr * 1024 + ((mq >> 1) * 16 + (kp >> 4) * 2 + (mq & 1)) * 8 + (u & 1) * 4);

    u32 hdst[8], mrem[8];
#pragma unroll
    for (int rk = 0; rk < 8; rk++) {
        hdst[rk] = mapa_sh(hb_l, (u32)rk) + off0;
        mrem[rk] = mapa_sh(mb_l, (u32)rk);
    }

    float c0 = 0.0f, h0 = 0.0f, c1 = 0.0f, h1 = 0.0f;
    u32 ph[4] = {0, 0, 0, 0};

#pragma unroll 1
    for (int t = 0; t < T_SZ; t++) {
        const int b = t & 1;

        if ((t & 127) == 0) {     // wait for workers' t-chunk
            if (tid == 0) {
                const int* ap = &g_chunk_done[t >> 7];
                int done;
                do {
                    asm volatile("ld.acquire.gpu.b32 %0, [%1];" : "=r"(done) : "l"(ap) : "memory");
                } while (done < TASKS_PER_CHUNK);
            }
            __syncthreads();
        }

#pragma unroll
        for (int g = 0; g < 2; g++) {
            const u32 moff = (u32)((g * 2 + b) * 8);

            float4 xq = make_float4(0.f, 0.f, 0.f, 0.f);
            if (ks < 4)
                xq = *(const float4*)(g_xgi + (g ? xgBase1 : xgBase0) + (size_t)t * 1024);

            if (t > 0) {
                mbar_wait(mb_l + moff, ph[g * 2 + b]);
                ph[g * 2 + b] ^= 1;
            }

            u64 acc[4][4];
#pragma unroll
            for (int r = 0; r < 4; r++)
#pragma unroll
                for (int gg = 0; gg < 4; gg++) acc[r][gg] = 0ull;

            const u64* hbp = hbuf + (g * 2 + b) * 512;
#pragma unroll
            for (int m2 = 0; m2 < 8; m2++) {
#pragma unroll
                for (int r = 0; r < 4; r++) {
                    ulonglong2 hv = *(const ulonglong2*)(hbp + r * 128 + m2 * 16 + ks * 2);
#pragma unroll
                    for (int gg = 0; gg < 4; gg++) {
                        acc[r][gg] = fma2(hv.x, wp[gg][2 * m2],     acc[r][gg]);
                        acc[r][gg] = fma2(hv.y, wp[gg][2 * m2 + 1], acc[r][gg]);
                    }
                }
            }

            if (t > 0 && tid == 0)
                mbar_expect(mb_l + moff, 4096);

            const bool pb = (ks & 1);
            const bool qb = (ks & 2);
            u64 kk[4];
#pragma unroll
            for (int gg = 0; gg < 4; gg++) {
                u64 sA = pb ? acc[0][gg] : acc[1][gg];
                u64 sB = pb ? acc[2][gg] : acc[3][gg];
                u64 rA = __shfl_xor_sync(0xffffffffu, sA, 1);
                u64 rB = __shfl_xor_sync(0xffffffffu, sB, 1);
                u64 k0 = add2(pb ? acc[1][gg] : acc[0][gg], rA);
                u64 k1 = add2(pb ? acc[3][gg] : acc[2][gg], rB);
                u64 s2 = qb ? k0 : k1;
                u64 r2 = __shfl_xor_sync(0xffffffffu, s2, 2);
                u64 kx = add2(qb ? k1 : k0, r2);
                kk[gg] = add2(kx, __shfl_xor_sync(0xffffffffu, kx, 4));
            }

            float hcur = 0.0f;
            if (ks < 4) {
                float e0, e1;
                unpk(kk[0], e0, e1); const float gi  = e0 + e1 + xq.x;
                unpk(kk[1], e0, e1); const float gf  = e0 + e1 + xq.y;
                unpk(kk[2], e0, e1); const float gg_ = e0 + e1 + xq.z;
                unpk(kk[3], e0, e1); const float go  = e0 + e1 + xq.w;

                float cv = g ? c1 : c0;
                cv = sigm(gf) * cv + sigm(gi) * tanh_(gg_);
                hcur = sigm(go) * tanh_(cv);
                if (g) { c1 = cv; h1 = hcur; } else { c0 = cv; h0 = hcur; }

                if (t < T_SZ - 1) {
                    const u32 po = (u32)(g * 8192 + (b ^ 1) * 4096);
                    const u32 mo = (u32)((g * 2 + (b ^ 1)) * 8);
#pragma unroll
                    for (int rk = 0; rk < 8; rk++)
                        st_async_f32(hdst[rk] + po, hcur, mrem[rk] + mo);
                }
            }

            {
                const float hs = __shfl_xor_sync(0xffffffffu, hcur, 4);
                if (ks >= 4)
                    out[(g ? outBase1 : outBase0) + (size_t)t * H_SZ] = hs;
            }
        }
    }

    if (ks < 4) {
        float* fin = out + (size_t)B_SZ * T_SZ * H_SZ;
        fin[(size_t)row0 * H_SZ + u] = h0;
        fin[(size_t)B_SZ * H_SZ + (size_t)row0 * H_SZ + u] = c0;
        fin[(size_t)row1 * H_SZ + u] = h1;
        fin[(size_t)B_SZ * H_SZ + (size_t)row1 * H_SZ + u] = c1;
    }
}

extern "C" void kernel_launch(void* const* d_in, const int* in_sizes, int n_in,
                              void* d_out, int out_size) {
    const float* x    = (const float*)d_in[0];
    const float* W_i  = (const float*)d_in[1];
    const float* W_h  = (const float*)d_in[2];
    const float* bias = (const float*)d_in[3];
    float* out = (float*)d_out;

    const int smem_bytes = 49280;
    cudaFuncSetAttribute(fused, cudaFuncAttributeMaxDynamicSharedMemorySize, smem_bytes);

    reset_ctrs<<<1, 32>>>();

    dim3 grid(8, 17);   // y<8: 8 scan clusters (64 CTAs); y>=8: 72 gemm workers
    fused<<<grid, 256, smem_bytes>>>(x, W_i, W_h, bias, out);
}